// round 3
// baseline (speedup 1.0000x reference)
#include <cuda_runtime.h>

#define BUF 4194304u
__device__ float g_scratch[5u * BUF];

// ================= SGEMM 128x128x8 body (M=4096,N=1024,K=1024) =================
__device__ __forceinline__ void sgemm_body(const float* __restrict__ A,
                                           const float* __restrict__ B,
                                           const float* __restrict__ R,
                                           float* __restrict__ C,
                                           float (*As)[128], float (*Bs)[128]) {
    const int t = threadIdx.x;
    const int n0 = blockIdx.x * 128, m0 = blockIdx.y * 128;
    const int tx = t & 15, ty = t >> 4;
    const int arow = t >> 1, acol = (t & 1) * 4;
    const int brow = t >> 5, bcol = (t & 31) * 4;
    const float* Ap = A + (size_t)(m0 + arow) * 1024 + acol;
    const float* Bp = B + (size_t)brow * 1024 + n0 + bcol;

    float acc[8][8];
#pragma unroll
    for (int i = 0; i < 8; i++)
#pragma unroll
        for (int j = 0; j < 8; j++) acc[i][j] = 0.f;

    for (int kb = 0; kb < 1024; kb += 8) {
        float4 av = *(const float4*)(Ap + kb);
        float4 bv = *(const float4*)(Bp + (size_t)kb * 1024);
        __syncthreads();
        As[acol + 0][arow] = av.x; As[acol + 1][arow] = av.y;
        As[acol + 2][arow] = av.z; As[acol + 3][arow] = av.w;
        *(float4*)&Bs[brow][bcol] = bv;
        __syncthreads();
#pragma unroll
        for (int k = 0; k < 8; k++) {
            float a[8], b[8];
            *(float4*)&a[0] = *(const float4*)&As[k][ty * 8];
            *(float4*)&a[4] = *(const float4*)&As[k][ty * 8 + 4];
            *(float4*)&b[0] = *(const float4*)&Bs[k][tx * 8];
            *(float4*)&b[4] = *(const float4*)&Bs[k][tx * 8 + 4];
#pragma unroll
            for (int i = 0; i < 8; i++)
#pragma unroll
                for (int j = 0; j < 8; j++) acc[i][j] += a[i] * b[j];
        }
    }
#pragma unroll
    for (int i = 0; i < 8; i++) {
        const int m = m0 + ty * 8 + i;
        float* cp = C + (size_t)m * 1024 + n0 + tx * 8;
        float4 o0 = make_float4(acc[i][0], acc[i][1], acc[i][2], acc[i][3]);
        float4 o1 = make_float4(acc[i][4], acc[i][5], acc[i][6], acc[i][7]);
        if (R) {
            const float* rp = R + (size_t)m * 1024 + n0 + tx * 8;
            float4 r0 = *(const float4*)rp, r1 = *(const float4*)(rp + 4);
            o0.x += r0.x; o0.y += r0.y; o0.z += r0.z; o0.w += r0.w;
            o1.x += r1.x; o1.y += r1.y; o1.z += r1.z; o1.w += r1.w;
        }
        *(float4*)cp = o0; *(float4*)(cp + 4) = o1;
    }
}

__global__ __launch_bounds__(256, 2)
void sgemm128(const float* __restrict__ A, const float* __restrict__ B,
              const float* __restrict__ R, float* __restrict__ C) {
    __shared__ float As[8][128], Bs[8][128];
    sgemm_body(A, B, R, C, As, Bs);
}

// fused Q/K/V projections: grid.z selects which
__global__ __launch_bounds__(256, 2)
void qkv_gemm(const float* __restrict__ iQ, const float* __restrict__ iK,
              const float* __restrict__ iV, const float* __restrict__ WQ,
              const float* __restrict__ WK, const float* __restrict__ WV,
              float* __restrict__ Qo, float* __restrict__ Ko, float* __restrict__ Vo) {
    __shared__ float As[8][128], Bs[8][128];
    const float* A; const float* B; float* C;
    if (blockIdx.z == 0)      { A = iQ; B = WQ; C = Qo; }
    else if (blockIdx.z == 1) { A = iK; B = WK; C = Ko; }
    else                      { A = iV; B = WV; C = Vo; }
    sgemm_body(A, B, nullptr, C, As, Bs);
}

// ================= fused attention, softmax over HEADS =================
// Q/K/V tiles: 256 rows (h*16 + r), 68-float stride, XOR-quad swizzle:
//   element d of row stored at row*68 + 4*((d>>2) ^ ((row>>2)&7)) + (d&3)
// scores: sc[q*273 + k*17 + h]
#define QS 0
#define KS 17408
#define VS 34816
#define SS 52224
#define SM_FLOATS (52224 + 4368)
#define SM_BYTES (SM_FLOATS * 4)

__device__ __forceinline__ void stage_tile(const float* __restrict__ src,
                                           float* __restrict__ dst, int t) {
    // 16 seq-rows x 1024 cols -> swizzled [256 rows][68]
#pragma unroll
    for (int i = 0; i < 8; i++) {
        const int f = i * 512 + t;        // float4 index 0..4095
        const int r = f >> 8;             // seq row 0..15
        const int c = f & 255;            // float4 col 0..255
        float4 v = *(const float4*)(src + (size_t)r * 1024 + c * 4);
        const int row = ((c >> 4) << 4) + r;              // h*16 + r
        const int q4 = (c & 15) ^ ((row >> 2) & 7);       // swizzled quad
        *(float4*)(dst + row * 68 + q4 * 4) = v;
    }
}

__global__ __launch_bounds__(512, 1)
void attn_kernel(const float* __restrict__ Q, const float* __restrict__ K,
                 const float* __restrict__ V, float* __restrict__ Ctx) {
    extern __shared__ float sm[];
    const int t = threadIdx.x;
    const int b = blockIdx.y;
    const int q0g = blockIdx.x << 4;

    const float* Qb = Q + ((size_t)b * 2048 + q0g) * 1024;
    const float* Kb = K + (size_t)b * 2048 * 1024;
    const float* Vb = V + (size_t)b * 2048 * 1024;

    stage_tile(Qb, sm + QS, t);

    const int h = t >> 5;
    const int w = t & 31;
    const int sq0 = ((w >> 3) & 3) * 4;   // score/context q block (4 rows)
    const int sk0 = (w & 7) * 2;          // score k block (2 cols)
    const int cv0 = (w & 7) * 8;          // context v block (8 dims)
    const int sxq = t >> 4, sxk = t & 15; // softmax pair (t < 256)

    // precompute swizzle keys for the 4 q rows and 2 k rows
    int qkey[4], kkey[2];
#pragma unroll
    for (int i = 0; i < 4; i++) qkey[i] = ((h * 16 + sq0 + i) >> 2) & 7;
#pragma unroll
    for (int j = 0; j < 2; j++) kkey[j] = ((h * 16 + sk0 + j) >> 2) & 7;

    float cacc[4][8];
#pragma unroll
    for (int i = 0; i < 4; i++)
#pragma unroll
        for (int j = 0; j < 8; j++) cacc[i][j] = 0.f;

    for (int kt = 0; kt < 128; kt++) {
        __syncthreads();
        stage_tile(Kb + (size_t)kt * 16 * 1024, sm + KS, t);
        stage_tile(Vb + (size_t)kt * 16 * 1024, sm + VS, t);
        __syncthreads();

        // ---- scores: 4q x 2k per thread, vectorized over d ----
        {
            float a00 = 0.f, a01 = 0.f, a10 = 0.f, a11 = 0.f;
            float a20 = 0.f, a21 = 0.f, a30 = 0.f, a31 = 0.f;
            const float* qp = &sm[QS + (h * 16 + sq0) * 68];
            const float* kp = &sm[KS + (h * 16 + sk0) * 68];
#pragma unroll 4
            for (int d4 = 0; d4 < 16; d4++) {
                float4 q0v = *(const float4*)(qp + 0 * 68 + ((d4 ^ qkey[0]) << 2));
                float4 q1v = *(const float4*)(qp + 1 * 68 + ((d4 ^ qkey[1]) << 2));
                float4 q2v = *(const float4*)(qp + 2 * 68 + ((d4 ^ qkey[2]) << 2));
                float4 q3v = *(const float4*)(qp + 3 * 68 + ((d4 ^ qkey[3]) << 2));
                float4 k0v = *(const float4*)(kp + 0 * 68 + ((d4 ^ kkey[0]) << 2));
                float4 k1v = *(const float4*)(kp + 1 * 68 + ((d4 ^ kkey[1]) << 2));
                a00 += q0v.x*k0v.x + q0v.y*k0v.y + q0v.z*k0v.z + q0v.w*k0v.w;
                a01 += q0v.x*k1v.x + q0v.y*k1v.y + q0v.z*k1v.z + q0v.w*k1v.w;
                a10 += q1v.x*k0v.x + q1v.y*k0v.y + q1v.z*k0v.z + q1v.w*k0v.w;
                a11 += q1v.x*k1v.x + q1v.y*k1v.y + q1v.z*k1v.z + q1v.w*k1v.w;
                a20 += q2v.x*k0v.x + q2v.y*k0v.y + q2v.z*k0v.z + q2v.w*k0v.w;
                a21 += q2v.x*k1v.x + q2v.y*k1v.y + q2v.z*k1v.z + q2v.w*k1v.w;
                a30 += q3v.x*k0v.x + q3v.y*k0v.y + q3v.z*k0v.z + q3v.w*k0v.w;
                a31 += q3v.x*k1v.x + q3v.y*k1v.y + q3v.z*k1v.z + q3v.w*k1v.w;
            }
            float* sp = &sm[SS + sq0 * 273 + sk0 * 17 + h];
            sp[0*273 + 0]  = a00 * 0.125f; sp[0*273 + 17] = a01 * 0.125f;
            sp[1*273 + 0]  = a10 * 0.125f; sp[1*273 + 17] = a11 * 0.125f;
            sp[2*273 + 0]  = a20 * 0.125f; sp[2*273 + 17] = a21 * 0.125f;
            sp[3*273 + 0]  = a30 * 0.125f; sp[3*273 + 17] = a31 * 0.125f;
        }
        __syncthreads();

        // ---- softmax over heads for one (q,k) pair ----
        if (t < 256) {
            float* p = &sm[SS + sxq * 273 + sxk * 17];
            float m = p[0];
#pragma unroll
            for (int hh = 1; hh < 16; hh++) m = fmaxf(m, p[hh]);
            float s = 0.f;
#pragma unroll
            for (int hh = 0; hh < 16; hh++) { float e = __expf(p[hh] - m); p[hh] = e; s += e; }
            float inv = 1.f / s;
#pragma unroll
            for (int hh = 0; hh < 16; hh++) p[hh] *= inv;
        }
        __syncthreads();

        // ---- context: 4q x 8v per thread ----
        {
            const int quad0 = cv0 >> 2;
#pragma unroll 4
            for (int k = 0; k < 16; k++) {
                const int row = h * 16 + k;
                const int key = (row >> 2) & 7;
                const float* vr = &sm[VS + row * 68];
                float4 v0 = *(const float4*)(vr + ((quad0 ^ key) << 2));
                float4 v1 = *(const float4*)(vr + (((quad0 + 1) ^ key) << 2));
                const float* ap = &sm[SS + sq0 * 273 + k * 17 + h];
#pragma unroll
                for (int i = 0; i < 4; i++) {
                    float a = ap[i * 273];
                    cacc[i][0] += a * v0.x; cacc[i][1] += a * v0.y;
                    cacc[i][2] += a * v0.z; cacc[i][3] += a * v0.w;
                    cacc[i][4] += a * v1.x; cacc[i][5] += a * v1.y;
                    cacc[i][6] += a * v1.z; cacc[i][7] += a * v1.w;
                }
            }
        }
    }

#pragma unroll
    for (int i = 0; i < 4; i++) {
        float* op = &Ctx[((size_t)b * 2048 + q0g + sq0 + i) * 1024 + h * 64 + cv0];
        *(float4*)op       = make_float4(cacc[i][0], cacc[i][1], cacc[i][2], cacc[i][3]);
        *(float4*)(op + 4) = make_float4(cacc[i][4], cacc[i][5], cacc[i][6], cacc[i][7]);
    }
}

// ================= LayerNorm over last dim (1024) =================
__global__ __launch_bounds__(256)
void ln_kernel(const float* __restrict__ x, const float* __restrict__ gamma,
               const float* __restrict__ beta, float* __restrict__ out) {
    __shared__ float red[16];
    const int row = blockIdx.x, t = threadIdx.x;
    float4 v = ((const float4*)(x + (size_t)row * 1024))[t];
    float s = v.x + v.y + v.z + v.w;
    float q = v.x * v.x + v.y * v.y + v.z * v.z + v.w * v.w;
#pragma unroll
    for (int o = 16; o > 0; o >>= 1) {
        s += __shfl_xor_sync(0xffffffffu, s, o);
        q += __shfl_xor_sync(0xffffffffu, q, o);
    }
    if ((t & 31) == 0) { red[t >> 5] = s; red[8 + (t >> 5)] = q; }
    __syncthreads();
    if (t < 8) {
        s = red[t]; q = red[8 + t];
#pragma unroll
        for (int o = 4; o > 0; o >>= 1) {
            s += __shfl_xor_sync(0xffu, s, o);
            q += __shfl_xor_sync(0xffu, q, o);
        }
        if (t == 0) { red[0] = s; red[1] = q; }
    }
    __syncthreads();
    const float mu = red[0] * (1.f / 1024.f);
    const float var = red[1] * (1.f / 1024.f) - mu * mu;
    const float inv = rsqrtf(var + 1e-5f);
    float4 g = ((const float4*)gamma)[t];
    float4 bb = ((const float4*)beta)[t];
    float4 o;
    o.x = (v.x - mu) * inv * g.x + bb.x;
    o.y = (v.y - mu) * inv * g.y + bb.y;
    o.z = (v.z - mu) * inv * g.z + bb.z;
    o.w = (v.w - mu) * inv * g.w + bb.w;
    ((float4*)(out + (size_t)row * 1024))[t] = o;
}

// ================= launch =================
extern "C" void kernel_launch(void* const* d_in, const int* in_sizes, int n_in,
                              void* d_out, int out_size) {
    const float* inQ = (const float*)d_in[0];
    const float* inK = (const float*)d_in[1];
    const float* inV = (const float*)d_in[2];
    const float* WQ  = (const float*)d_in[3];
    const float* WK  = (const float*)d_in[4];
    const float* WV  = (const float*)d_in[5];
    const float* WO  = (const float*)d_in[6];
    const float* gam = (const float*)d_in[7];
    const float* bet = (const float*)d_in[8];
    float* out = (float*)d_out;

    float* base = nullptr;
    cudaGetSymbolAddress((void**)&base, g_scratch);
    float* Qb = base;
    float* Kb = base + BUF;
    float* Vb = base + 2 * BUF;
    float* Cx = base + 3 * BUF;
    float* Xb = base + 4 * BUF;

    qkv_gemm<<<dim3(8, 32, 3), 256>>>(inQ, inK, inV, WQ, WK, WV, Qb, Kb, Vb);

    cudaFuncSetAttribute(attn_kernel, cudaFuncAttributeMaxDynamicSharedMemorySize, SM_BYTES);
    attn_kernel<<<dim3(128, 2), 512, SM_BYTES>>>(Qb, Kb, Vb, Cx);

    sgemm128<<<dim3(8, 32), 256>>>(Cx, WO, inQ, Xb);
    ln_kernel<<<4096, 256>>>(Xb, gam, bet, out);
}

// round 4
// speedup vs baseline: 1.5771x; 1.5771x over previous
#include <cuda_runtime.h>

#define BUF 4194304u
__device__ float g_scratch[5u * BUF];

// ================= SGEMM 128x128x8 (M=4096,N=1024,K=1024), fp32 =================
__global__ __launch_bounds__(256, 2)
void sgemm128(const float* __restrict__ A, const float* __restrict__ B,
              const float* __restrict__ R, float* __restrict__ C) {
    __shared__ float As[8][128], Bs[8][128];
    const int t = threadIdx.x;
    const int n0 = blockIdx.x * 128, m0 = blockIdx.y * 128;
    const int tx = t & 15, ty = t >> 4;
    const int arow = t >> 1, acol = (t & 1) * 4;
    const int brow = t >> 5, bcol = (t & 31) * 4;
    const float* Ap = A + (size_t)(m0 + arow) * 1024 + acol;
    const float* Bp = B + (size_t)brow * 1024 + n0 + bcol;

    float acc[8][8];
#pragma unroll
    for (int i = 0; i < 8; i++)
#pragma unroll
        for (int j = 0; j < 8; j++) acc[i][j] = 0.f;

    for (int kb = 0; kb < 1024; kb += 8) {
        float4 av = *(const float4*)(Ap + kb);
        float4 bv = *(const float4*)(Bp + (size_t)kb * 1024);
        __syncthreads();
        As[acol + 0][arow] = av.x; As[acol + 1][arow] = av.y;
        As[acol + 2][arow] = av.z; As[acol + 3][arow] = av.w;
        *(float4*)&Bs[brow][bcol] = bv;
        __syncthreads();
#pragma unroll
        for (int k = 0; k < 8; k++) {
            float a[8], b[8];
            *(float4*)&a[0] = *(const float4*)&As[k][ty * 8];
            *(float4*)&a[4] = *(const float4*)&As[k][ty * 8 + 4];
            *(float4*)&b[0] = *(const float4*)&Bs[k][tx * 8];
            *(float4*)&b[4] = *(const float4*)&Bs[k][tx * 8 + 4];
#pragma unroll
            for (int i = 0; i < 8; i++)
#pragma unroll
                for (int j = 0; j < 8; j++) acc[i][j] += a[i] * b[j];
        }
    }
#pragma unroll
    for (int i = 0; i < 8; i++) {
        const int m = m0 + ty * 8 + i;
        float* cp = C + (size_t)m * 1024 + n0 + tx * 8;
        float4 o0 = make_float4(acc[i][0], acc[i][1], acc[i][2], acc[i][3]);
        float4 o1 = make_float4(acc[i][4], acc[i][5], acc[i][6], acc[i][7]);
        if (R) {
            const float* rp = R + (size_t)m * 1024 + n0 + tx * 8;
            float4 r0 = *(const float4*)rp, r1 = *(const float4*)(rp + 4);
            o0.x += r0.x; o0.y += r0.y; o0.z += r0.z; o0.w += r0.w;
            o1.x += r1.x; o1.y += r1.y; o1.z += r1.z; o1.w += r1.w;
        }
        *(float4*)cp = o0; *(float4*)(cp + 4) = o1;
    }
}

// ================= tf32 mma helpers =================
__device__ __forceinline__ unsigned f2tf(float f) {
    unsigned u;
    asm("cvt.rna.tf32.f32 %0, %1;" : "=r"(u) : "f"(f));
    return u;
}
__device__ __forceinline__ unsigned ldu(const float* p) {
    return __float_as_uint(*p);
}
__device__ __forceinline__ void mma_tf32(float& c0, float& c1, float& c2, float& c3,
                                         unsigned a0, unsigned a1, unsigned a2, unsigned a3,
                                         unsigned b0, unsigned b1) {
    asm volatile("mma.sync.aligned.m16n8k8.row.col.f32.tf32.tf32.f32 "
                 "{%0,%1,%2,%3}, {%4,%5,%6,%7}, {%8,%9}, {%0,%1,%2,%3};"
                 : "+f"(c0), "+f"(c1), "+f"(c2), "+f"(c3)
                 : "r"(a0), "r"(a1), "r"(a2), "r"(a3), "r"(b0), "r"(b1));
}

// ================= fused attention, softmax over HEADS, tf32 tensor cores =====
// Q/K/V tiles: row = h*16 + seq_row, stride 68 floats (scalar frag loads are
// conflict-free: addr mod 32 = 4*group + tig). Values stored tf32-rounded.
// scores: sc[q*273 + k*17 + h] (fp32).
#define QS 0
#define KS 17408
#define VS 34816
#define SS 52224
#define SM_FLOATS (52224 + 4368)
#define SM_BYTES (SM_FLOATS * 4)

__device__ __forceinline__ void stage_tile_tf32(const float* __restrict__ src,
                                                float* __restrict__ dst, int t) {
    // 16 seq rows x 1024 cols -> [256 rows][68], tf32-rounded
#pragma unroll
    for (int i = 0; i < 8; i++) {
        const int f = i * 512 + t;     // float4 index 0..4095
        const int r = f >> 8;          // seq row 0..15
        const int c = f & 255;         // float4 col 0..255
        float4 v = *(const float4*)(src + (size_t)r * 1024 + c * 4);
        const int row = ((c >> 4) << 4) + r;   // h*16 + r
        float4 w;
        w.x = __uint_as_float(f2tf(v.x));
        w.y = __uint_as_float(f2tf(v.y));
        w.z = __uint_as_float(f2tf(v.z));
        w.w = __uint_as_float(f2tf(v.w));
        *(float4*)(dst + row * 68 + (c & 15) * 4) = w;
    }
}

__global__ __launch_bounds__(512, 1)
void attn_kernel(const float* __restrict__ Q, const float* __restrict__ K,
                 const float* __restrict__ V, float* __restrict__ Ctx) {
    extern __shared__ float sm[];
    const int t = threadIdx.x;
    const int b = blockIdx.y;
    const int q0g = blockIdx.x << 4;

    const float* Qb = Q + ((size_t)b * 2048 + q0g) * 1024;
    const float* Kb = K + (size_t)b * 2048 * 1024;
    const float* Vb = V + (size_t)b * 2048 * 1024;

    stage_tile_tf32(Qb, sm + QS, t);
    __syncthreads();

    const int h    = t >> 5;        // warp = head
    const int lane = t & 31;
    const int g    = lane >> 2;     // groupID
    const int tig  = lane & 3;      // thread-in-group

    // preload Q fragments for this head: aq[kstep][0..3]
    unsigned aq[8][4];
    {
        const float* qp = &sm[QS + (h * 16 + g) * 68];
#pragma unroll
        for (int ks = 0; ks < 8; ks++) {
            aq[ks][0] = ldu(qp + ks * 8 + tig);
            aq[ks][1] = ldu(qp + 8 * 68 + ks * 8 + tig);
            aq[ks][2] = ldu(qp + ks * 8 + tig + 4);
            aq[ks][3] = ldu(qp + 8 * 68 + ks * 8 + tig + 4);
        }
    }

    float cacc[8][4];   // context C frags: [ntile][c0..c3], 16q x 64d per head
#pragma unroll
    for (int n = 0; n < 8; n++)
#pragma unroll
        for (int j = 0; j < 4; j++) cacc[n][j] = 0.f;

    const int sxq = t >> 4, sxk = t & 15;  // softmax pair (t < 256)

    for (int kt = 0; kt < 128; kt++) {
        __syncthreads();
        stage_tile_tf32(Kb + (size_t)kt * 16 * 1024, sm + KS, t);
        stage_tile_tf32(Vb + (size_t)kt * 16 * 1024, sm + VS, t);
        __syncthreads();

        // ---- scores: 16q x 16k per warp (2 ntiles x 8 ksteps of mma) ----
#pragma unroll
        for (int nt = 0; nt < 2; nt++) {
            float c0 = 0.f, c1 = 0.f, c2 = 0.f, c3 = 0.f;
            const float* kp = &sm[KS + (h * 16 + nt * 8 + g) * 68];
#pragma unroll
            for (int ks = 0; ks < 8; ks++) {
                unsigned b0 = ldu(kp + ks * 8 + tig);
                unsigned b1 = ldu(kp + ks * 8 + tig + 4);
                mma_tf32(c0, c1, c2, c3, aq[ks][0], aq[ks][1], aq[ks][2], aq[ks][3], b0, b1);
            }
            float* sp = &sm[SS + g * 273 + (nt * 8 + 2 * tig) * 17 + h];
            sp[0]            = c0 * 0.125f;
            sp[17]           = c1 * 0.125f;
            sp[8 * 273]      = c2 * 0.125f;
            sp[8 * 273 + 17] = c3 * 0.125f;
        }
        __syncthreads();

        // ---- softmax over the 16 heads for one (q,k) pair ----
        if (t < 256) {
            float* p = &sm[SS + sxq * 273 + sxk * 17];
            float m = p[0];
#pragma unroll
            for (int hh = 1; hh < 16; hh++) m = fmaxf(m, p[hh]);
            float s = 0.f;
#pragma unroll
            for (int hh = 0; hh < 16; hh++) { float e = __expf(p[hh] - m); p[hh] = e; s += e; }
            float inv = 1.f / s;
#pragma unroll
            for (int hh = 0; hh < 16; hh++) p[hh] *= inv;
        }
        __syncthreads();

        // ---- context: attn[16q,16k] @ V[16k,64d] per head ----
#pragma unroll
        for (int ks = 0; ks < 2; ks++) {
            unsigned a0 = f2tf(sm[SS + g * 273 + (ks * 8 + tig) * 17 + h]);
            unsigned a1 = f2tf(sm[SS + (g + 8) * 273 + (ks * 8 + tig) * 17 + h]);
            unsigned a2 = f2tf(sm[SS + g * 273 + (ks * 8 + tig + 4) * 17 + h]);
            unsigned a3 = f2tf(sm[SS + (g + 8) * 273 + (ks * 8 + tig + 4) * 17 + h]);
            const float* vlo = &sm[VS + (h * 16 + ks * 8 + tig) * 68];
            const float* vhi = &sm[VS + (h * 16 + ks * 8 + tig + 4) * 68];
#pragma unroll
            for (int nt = 0; nt < 8; nt++) {
                unsigned b0 = ldu(vlo + nt * 8 + g);
                unsigned b1 = ldu(vhi + nt * 8 + g);
                mma_tf32(cacc[nt][0], cacc[nt][1], cacc[nt][2], cacc[nt][3],
                         a0, a1, a2, a3, b0, b1);
            }
        }
    }

    // ---- write context: Ctx[(b*2048+q0g+q)*1024 + h*64 + d] ----
#pragma unroll
    for (int nt = 0; nt < 8; nt++) {
        const size_t base = ((size_t)b * 2048 + q0g + g) * 1024 + h * 64 + nt * 8 + 2 * tig;
        *(float2*)&Ctx[base]              = make_float2(cacc[nt][0], cacc[nt][1]);
        *(float2*)&Ctx[base + 8 * 1024]   = make_float2(cacc[nt][2], cacc[nt][3]);
    }
}

// ================= LayerNorm over last dim (1024) =================
__global__ __launch_bounds__(256)
void ln_kernel(const float* __restrict__ x, const float* __restrict__ gamma,
               const float* __restrict__ beta, float* __restrict__ out) {
    __shared__ float red[16];
    const int row = blockIdx.x, t = threadIdx.x;
    float4 v = ((const float4*)(x + (size_t)row * 1024))[t];
    float s = v.x + v.y + v.z + v.w;
    float q = v.x * v.x + v.y * v.y + v.z * v.z + v.w * v.w;
#pragma unroll
    for (int o = 16; o > 0; o >>= 1) {
        s += __shfl_xor_sync(0xffffffffu, s, o);
        q += __shfl_xor_sync(0xffffffffu, q, o);
    }
    if ((t & 31) == 0) { red[t >> 5] = s; red[8 + (t >> 5)] = q; }
    __syncthreads();
    if (t < 8) {
        s = red[t]; q = red[8 + t];
#pragma unroll
        for (int o = 4; o > 0; o >>= 1) {
            s += __shfl_xor_sync(0xffu, s, o);
            q += __shfl_xor_sync(0xffu, q, o);
        }
        if (t == 0) { red[0] = s; red[1] = q; }
    }
    __syncthreads();
    const float mu = red[0] * (1.f / 1024.f);
    const float var = red[1] * (1.f / 1024.f) - mu * mu;
    const float inv = rsqrtf(var + 1e-5f);
    float4 g = ((const float4*)gamma)[t];
    float4 bb = ((const float4*)beta)[t];
    float4 o;
    o.x = (v.x - mu) * inv * g.x + bb.x;
    o.y = (v.y - mu) * inv * g.y + bb.y;
    o.z = (v.z - mu) * inv * g.z + bb.z;
    o.w = (v.w - mu) * inv * g.w + bb.w;
    ((float4*)(out + (size_t)row * 1024))[t] = o;
}

// ================= launch =================
extern "C" void kernel_launch(void* const* d_in, const int* in_sizes, int n_in,
                              void* d_out, int out_size) {
    const float* inQ = (const float*)d_in[0];
    const float* inK = (const float*)d_in[1];
    const float* inV = (const float*)d_in[2];
    const float* WQ  = (const float*)d_in[3];
    const float* WK  = (const float*)d_in[4];
    const float* WV  = (const float*)d_in[5];
    const float* WO  = (const float*)d_in[6];
    const float* gam = (const float*)d_in[7];
    const float* bet = (const float*)d_in[8];
    float* out = (float*)d_out;

    float* base = nullptr;
    cudaGetSymbolAddress((void**)&base, g_scratch);
    float* Qb = base;
    float* Kb = base + BUF;
    float* Vb = base + 2 * BUF;
    float* Cx = base + 3 * BUF;
    float* Xb = base + 4 * BUF;

    dim3 gg(8, 32);
    sgemm128<<<gg, 256>>>(inQ, WQ, nullptr, Qb);
    sgemm128<<<gg, 256>>>(inK, WK, nullptr, Kb);
    sgemm128<<<gg, 256>>>(inV, WV, nullptr, Vb);

    cudaFuncSetAttribute(attn_kernel, cudaFuncAttributeMaxDynamicSharedMemorySize, SM_BYTES);
    attn_kernel<<<dim3(128, 2), 512, SM_BYTES>>>(Qb, Kb, Vb, Cx);

    sgemm128<<<gg, 256>>>(Cx, WO, inQ, Xb);
    ln_kernel<<<4096, 256>>>(Xb, gam, bet, out);
}

// round 5
// speedup vs baseline: 1.6863x; 1.0692x over previous
#include <cuda_runtime.h>

#define BUF 4194304u
__device__ float g_scratch[5u * BUF];

// ================= SGEMM 128x128x8 (M=4096,N=1024,K=1024), fp32 =================
__global__ __launch_bounds__(256, 2)
void sgemm128(const float* __restrict__ A, const float* __restrict__ B,
              const float* __restrict__ R, float* __restrict__ C) {
    __shared__ float As[8][128], Bs[8][128];
    const int t = threadIdx.x;
    const int n0 = blockIdx.x * 128, m0 = blockIdx.y * 128;
    const int tx = t & 15, ty = t >> 4;
    const int arow = t >> 1, acol = (t & 1) * 4;
    const int brow = t >> 5, bcol = (t & 31) * 4;
    const float* Ap = A + (size_t)(m0 + arow) * 1024 + acol;
    const float* Bp = B + (size_t)brow * 1024 + n0 + bcol;

    float acc[8][8];
#pragma unroll
    for (int i = 0; i < 8; i++)
#pragma unroll
        for (int j = 0; j < 8; j++) acc[i][j] = 0.f;

    for (int kb = 0; kb < 1024; kb += 8) {
        float4 av = *(const float4*)(Ap + kb);
        float4 bv = *(const float4*)(Bp + (size_t)kb * 1024);
        __syncthreads();
        As[acol + 0][arow] = av.x; As[acol + 1][arow] = av.y;
        As[acol + 2][arow] = av.z; As[acol + 3][arow] = av.w;
        *(float4*)&Bs[brow][bcol] = bv;
        __syncthreads();
#pragma unroll
        for (int k = 0; k < 8; k++) {
            float a[8], b[8];
            *(float4*)&a[0] = *(const float4*)&As[k][ty * 8];
            *(float4*)&a[4] = *(const float4*)&As[k][ty * 8 + 4];
            *(float4*)&b[0] = *(const float4*)&Bs[k][tx * 8];
            *(float4*)&b[4] = *(const float4*)&Bs[k][tx * 8 + 4];
#pragma unroll
            for (int i = 0; i < 8; i++)
#pragma unroll
                for (int j = 0; j < 8; j++) acc[i][j] += a[i] * b[j];
        }
    }
#pragma unroll
    for (int i = 0; i < 8; i++) {
        const int m = m0 + ty * 8 + i;
        float* cp = C + (size_t)m * 1024 + n0 + tx * 8;
        float4 o0 = make_float4(acc[i][0], acc[i][1], acc[i][2], acc[i][3]);
        float4 o1 = make_float4(acc[i][4], acc[i][5], acc[i][6], acc[i][7]);
        if (R) {
            const float* rp = R + (size_t)m * 1024 + n0 + tx * 8;
            float4 r0 = *(const float4*)rp, r1 = *(const float4*)(rp + 4);
            o0.x += r0.x; o0.y += r0.y; o0.z += r0.z; o0.w += r0.w;
            o1.x += r1.x; o1.y += r1.y; o1.z += r1.z; o1.w += r1.w;
        }
        *(float4*)cp = o0; *(float4*)(cp + 4) = o1;
    }
}

// ================= tf32 mma helpers =================
__device__ __forceinline__ unsigned f2tf(float f) {
    unsigned u;
    asm("cvt.rna.tf32.f32 %0, %1;" : "=r"(u) : "f"(f));
    return u;
}
__device__ __forceinline__ unsigned ldu(const float* p) { return __float_as_uint(*p); }
__device__ __forceinline__ void mma_tf32(float& c0, float& c1, float& c2, float& c3,
                                         unsigned a0, unsigned a1, unsigned a2, unsigned a3,
                                         unsigned b0, unsigned b1) {
    asm volatile("mma.sync.aligned.m16n8k8.row.col.f32.tf32.tf32.f32 "
                 "{%0,%1,%2,%3}, {%4,%5,%6,%7}, {%8,%9}, {%0,%1,%2,%3};"
                 : "+f"(c0), "+f"(c1), "+f"(c2), "+f"(c3)
                 : "r"(a0), "r"(a1), "r"(a2), "r"(a3), "r"(b0), "r"(b1));
}

// ================= fused attention, softmax over HEADS, tf32 + cp.async =====
// smem float offsets: KA=0, KB=17408, VV=34816 (each [256 rows][68]), SS=52224
#define KA 0
#define KB 17408
#define VV 34816
#define SS 52224
#define SM_FLOATS (52224 + 4368)
#define SM_BYTES (SM_FLOATS * 4)

#define CP_COMMIT()  asm volatile("cp.async.commit_group;" ::: "memory")
#define CP_WAIT(N)   asm volatile("cp.async.wait_group %0;" :: "n"(N) : "memory")

// 16 seq rows x 1024 floats -> [row = h*16+r][68], 16B granules via cp.async
__device__ __forceinline__ void stage_async(const float* __restrict__ src,
                                            unsigned dst_u32, int t) {
#pragma unroll
    for (int i = 0; i < 8; i++) {
        const int f = i * 512 + t;          // float4 index 0..4095
        const int r = f >> 8;               // seq row 0..15
        const int c = f & 255;              // float4 col 0..255
        const int row = ((c >> 4) << 4) + r;
        const unsigned dst = dst_u32 + (unsigned)(row * 68 + (c & 15) * 4) * 4u;
        const float* g = src + (size_t)r * 1024 + c * 4;
        asm volatile("cp.async.cg.shared.global [%0], [%1], 16;" :: "r"(dst), "l"(g));
    }
}

__global__ __launch_bounds__(512, 1)
void attn_kernel(const float* __restrict__ Q, const float* __restrict__ K,
                 const float* __restrict__ V, float* __restrict__ Ctx) {
    extern __shared__ float sm[];
    unsigned smb;
    asm("{ .reg .u64 a; cvta.to.shared.u64 a, %1; cvt.u32.u64 %0, a; }"
        : "=r"(smb) : "l"(sm));

    const int t = threadIdx.x;
    const int b = blockIdx.y;
    const int q0g = blockIdx.x << 4;

    const float* Qb = Q + ((size_t)b * 2048 + q0g) * 1024;
    const float* Kb = K + (size_t)b * 2048 * 1024;
    const float* Vb = V + (size_t)b * 2048 * 1024;

    const int h    = t >> 5;        // warp = head
    const int lane = t & 31;
    const int g    = lane >> 2;     // groupID
    const int tig  = lane & 3;      // thread-in-group

    // ---- stage Q into V buffer, preload fragments ----
    stage_async(Qb, smb + VV * 4u, t);
    CP_COMMIT();
    CP_WAIT(0);
    __syncthreads();

    unsigned aq[8][4];
    {
        const float* qp = &sm[VV + (h * 16 + g) * 68];
#pragma unroll
        for (int ks = 0; ks < 8; ks++) {
            aq[ks][0] = ldu(qp + ks * 8 + tig);
            aq[ks][1] = ldu(qp + 8 * 68 + ks * 8 + tig);
            aq[ks][2] = ldu(qp + ks * 8 + tig + 4);
            aq[ks][3] = ldu(qp + 8 * 68 + ks * 8 + tig + 4);
        }
    }
    // prefetch K0 (KA) while frags load; then V0 after all warps done with VV
    stage_async(Kb, smb + KA * 4u, t);
    CP_COMMIT();                       // pending: K0
    __syncthreads();                   // VV free
    stage_async(Vb, smb + VV * 4u, t);
    CP_COMMIT();                       // pending: K0, V0

    float cacc[8][4];
#pragma unroll
    for (int n = 0; n < 8; n++)
#pragma unroll
        for (int j = 0; j < 4; j++) cacc[n][j] = 0.f;

    const int sxq = t >> 4, sxk = t & 15;   // softmax pair (t < 256)

    for (int kt = 0; kt < 128; kt++) {
        const int cur = (kt & 1) ? KB : KA;
        const int nxt = (kt & 1) ? KA : KB;

        CP_WAIT(1);        // K(kt) arrived (leaves V(kt) in flight)
        __syncthreads();

        // ---- scores: 16q x 16k per warp ----
#pragma unroll
        for (int nt = 0; nt < 2; nt++) {
            float c0 = 0.f, c1 = 0.f, c2 = 0.f, c3 = 0.f;
            const float* kp = &sm[cur + (h * 16 + nt * 8 + g) * 68];
#pragma unroll
            for (int ks = 0; ks < 8; ks++) {
                unsigned b0 = ldu(kp + ks * 8 + tig);
                unsigned b1 = ldu(kp + ks * 8 + tig + 4);
                mma_tf32(c0, c1, c2, c3, aq[ks][0], aq[ks][1], aq[ks][2], aq[ks][3], b0, b1);
            }
            float* sp = &sm[SS + g * 273 + (nt * 8 + 2 * tig) * 17 + h];
            sp[0]            = c0 * 0.125f;
            sp[17]           = c1 * 0.125f;
            sp[8 * 273]      = c2 * 0.125f;
            sp[8 * 273 + 17] = c3 * 0.125f;
        }

        // prefetch K(kt+1) into the other buffer (free since last iter)
        {
            const int kt2 = (kt + 1 < 128) ? kt + 1 : 127;
            stage_async(Kb + (size_t)kt2 * 16 * 1024, smb + (unsigned)nxt * 4u, t);
            CP_COMMIT();   // pending: V(kt), K(kt+1)
        }
        __syncthreads();   // scores visible

        // ---- softmax over the 16 heads for one (q,k) pair ----
        if (t < 256) {
            float* p = &sm[SS + sxq * 273 + sxk * 17];
            float m = p[0];
#pragma unroll
            for (int hh = 1; hh < 16; hh++) m = fmaxf(m, p[hh]);
            float s = 0.f;
#pragma unroll
            for (int hh = 0; hh < 16; hh++) { float e = __expf(p[hh] - m); p[hh] = e; s += e; }
            float inv = 1.f / s;
#pragma unroll
            for (int hh = 0; hh < 16; hh++) p[hh] *= inv;
        }

        CP_WAIT(1);        // V(kt) arrived (leaves K(kt+1) in flight)
        __syncthreads();   // softmax + V visible

        // ---- context: attn[16q,16k] @ V[16k,64d] per head ----
#pragma unroll
        for (int ks = 0; ks < 2; ks++) {
            unsigned a0 = f2tf(sm[SS + g * 273 + (ks * 8 + tig) * 17 + h]);
            unsigned a1 = f2tf(sm[SS + (g + 8) * 273 + (ks * 8 + tig) * 17 + h]);
            unsigned a2 = f2tf(sm[SS + g * 273 + (ks * 8 + tig + 4) * 17 + h]);
            unsigned a3 = f2tf(sm[SS + (g + 8) * 273 + (ks * 8 + tig + 4) * 17 + h]);
            const float* vlo = &sm[VV + (h * 16 + ks * 8 + tig) * 68];
            const float* vhi = &sm[VV + (h * 16 + ks * 8 + tig + 4) * 68];
#pragma unroll
            for (int nt = 0; nt < 8; nt++) {
                unsigned b0 = ldu(vlo + nt * 8 + g);
                unsigned b1 = ldu(vhi + nt * 8 + g);
                mma_tf32(cacc[nt][0], cacc[nt][1], cacc[nt][2], cacc[nt][3],
                         a0, a1, a2, a3, b0, b1);
            }
        }
        __syncthreads();   // V buffer free

        if (kt + 1 < 128) {
            stage_async(Vb + (size_t)(kt + 1) * 16 * 1024, smb + VV * 4u, t);
            CP_COMMIT();   // pending: K(kt+1), V(kt+1)
        }
    }

    // ---- write context ----
#pragma unroll
    for (int nt = 0; nt < 8; nt++) {
        const size_t base = ((size_t)b * 2048 + q0g + g) * 1024 + h * 64 + nt * 8 + 2 * tig;
        *(float2*)&Ctx[base]            = make_float2(cacc[nt][0], cacc[nt][1]);
        *(float2*)&Ctx[base + 8 * 1024] = make_float2(cacc[nt][2], cacc[nt][3]);
    }
}

// ================= LayerNorm over last dim (1024) =================
__global__ __launch_bounds__(256)
void ln_kernel(const float* __restrict__ x, const float* __restrict__ gamma,
               const float* __restrict__ beta, float* __restrict__ out) {
    __shared__ float red[16];
    const int row = blockIdx.x, t = threadIdx.x;
    float4 v = ((const float4*)(x + (size_t)row * 1024))[t];
    float s = v.x + v.y + v.z + v.w;
    float q = v.x * v.x + v.y * v.y + v.z * v.z + v.w * v.w;
#pragma unroll
    for (int o = 16; o > 0; o >>= 1) {
        s += __shfl_xor_sync(0xffffffffu, s, o);
        q += __shfl_xor_sync(0xffffffffu, q, o);
    }
    if ((t & 31) == 0) { red[t >> 5] = s; red[8 + (t >> 5)] = q; }
    __syncthreads();
    if (t < 8) {
        s = red[t]; q = red[8 + t];
#pragma unroll
        for (int o = 4; o > 0; o >>= 1) {
            s += __shfl_xor_sync(0xffu, s, o);
            q += __shfl_xor_sync(0xffu, q, o);
        }
        if (t == 0) { red[0] = s; red[1] = q; }
    }
    __syncthreads();
    const float mu = red[0] * (1.f / 1024.f);
    const float var = red[1] * (1.f / 1024.f) - mu * mu;
    const float inv = rsqrtf(var + 1e-5f);
    float4 g = ((const float4*)gamma)[t];
    float4 bb = ((const float4*)beta)[t];
    float4 o;
    o.x = (v.x - mu) * inv * g.x + bb.x;
    o.y = (v.y - mu) * inv * g.y + bb.y;
    o.z = (v.z - mu) * inv * g.z + bb.z;
    o.w = (v.w - mu) * inv * g.w + bb.w;
    ((float4*)(out + (size_t)row * 1024))[t] = o;
}

// ================= launch =================
extern "C" void kernel_launch(void* const* d_in, const int* in_sizes, int n_in,
                              void* d_out, int out_size) {
    const float* inQ = (const float*)d_in[0];
    const float* inK = (const float*)d_in[1];
    const float* inV = (const float*)d_in[2];
    const float* WQ  = (const float*)d_in[3];
    const float* WK  = (const float*)d_in[4];
    const float* WV  = (const float*)d_in[5];
    const float* WO  = (const float*)d_in[6];
    const float* gam = (const float*)d_in[7];
    const float* bet = (const float*)d_in[8];
    float* out = (float*)d_out;

    float* base = nullptr;
    cudaGetSymbolAddress((void**)&base, g_scratch);
    float* Qb = base;
    float* Kb = base + BUF;
    float* Vb = base + 2 * BUF;
    float* Cx = base + 3 * BUF;
    float* Xb = base + 4 * BUF;

    dim3 gg(8, 32);
    sgemm128<<<gg, 256>>>(inQ, WQ, nullptr, Qb);
    sgemm128<<<gg, 256>>>(inK, WK, nullptr, Kb);
    sgemm128<<<gg, 256>>>(inV, WV, nullptr, Vb);

    cudaFuncSetAttribute(attn_kernel, cudaFuncAttributeMaxDynamicSharedMemorySize, SM_BYTES);
    attn_kernel<<<dim3(128, 2), 512, SM_BYTES>>>(Qb, Kb, Vb, Cx);

    sgemm128<<<gg, 256>>>(Cx, WO, inQ, Xb);
    ln_kernel<<<4096, 256>>>(Xb, gam, bet, out);
}

// round 6
// speedup vs baseline: 2.3002x; 1.3640x over previous
#include <cuda_runtime.h>

#define BUF 4194304u
__device__ float g_scratch[5u * BUF];

// ================= common helpers =================
__device__ __forceinline__ unsigned f2tf(float f) {
    unsigned u; asm("cvt.rna.tf32.f32 %0, %1;" : "=r"(u) : "f"(f)); return u;
}
__device__ __forceinline__ unsigned ldu(const float* p) { return __float_as_uint(*p); }
__device__ __forceinline__ void mma_tf32(float& c0, float& c1, float& c2, float& c3,
                                         unsigned a0, unsigned a1, unsigned a2, unsigned a3,
                                         unsigned b0, unsigned b1) {
    asm volatile("mma.sync.aligned.m16n8k8.row.col.f32.tf32.tf32.f32 "
                 "{%0,%1,%2,%3}, {%4,%5,%6,%7}, {%8,%9}, {%0,%1,%2,%3};"
                 : "+f"(c0), "+f"(c1), "+f"(c2), "+f"(c3)
                 : "r"(a0), "r"(a1), "r"(a2), "r"(a3), "r"(b0), "r"(b1));
}
#define CP_COMMIT()  asm volatile("cp.async.commit_group;" ::: "memory")
#define CP_WAIT(N)   asm volatile("cp.async.wait_group %0;" :: "n"(N) : "memory")
__device__ __forceinline__ void cp16(unsigned dst, const float* src) {
    asm volatile("cp.async.cg.shared.global [%0], [%1], 16;" :: "r"(dst), "l"(src));
}

// ================= tf32 tensor GEMM (M=4096,N=1024,K=1024) =================
// CTA 128x128, 8 warps m64xn32, k-chunk 32, double-buffered cp.async.
// A smem [m][32] XOR-quad swizzle; B smem [k][136].
// SPLIT=3: 3xTF32 emulation (near-fp32); SPLIT=1: plain tf32 (RNA-rounded).
#define GA0 0
#define GA1 4096
#define GB0 8192
#define GB1 12544
#define GSM_BYTES ((12544 + 4352) * 4)

template <int SPLIT>
__global__ __launch_bounds__(256)
void gemm_tf32(const float* __restrict__ A, const float* __restrict__ B,
               const float* __restrict__ R, float* __restrict__ C) {
    extern __shared__ float smg[];
    unsigned smb;
    asm("{ .reg .u64 a; cvta.to.shared.u64 a, %1; cvt.u32.u64 %0, a; }"
        : "=r"(smb) : "l"(smg));
    const int t = threadIdx.x;
    const int n0 = blockIdx.x * 128, m0 = blockIdx.y * 128;
    const int lane = t & 31, w = t >> 5, g = lane >> 2, tig = lane & 3;
    const int m0w = (w >> 2) * 64, n0w = (w & 3) * 32;

    float acc[4][4][4];
#pragma unroll
    for (int mf = 0; mf < 4; mf++)
#pragma unroll
        for (int nf = 0; nf < 4; nf++)
#pragma unroll
            for (int r = 0; r < 4; r++) acc[mf][nf][r] = 0.f;

    auto stage = [&](int kc, int buf) {
        const float* Ab = A + (size_t)m0 * 1024 + kc * 32;
        const unsigned abase = smb + (buf ? GA1 * 4u : 0u);
#pragma unroll
        for (int i = 0; i < 4; i++) {
            const int gi = i * 256 + t;
            const int m = gi >> 3, kq = gi & 7;
            cp16(abase + (unsigned)(m * 32 + 4 * (kq ^ (m & 7))) * 4u,
                 Ab + (size_t)m * 1024 + kq * 4);
        }
        const float* Bb = B + (size_t)kc * 32 * 1024 + n0;
        const unsigned bbase = smb + (unsigned)(buf ? GB1 : GB0) * 4u;
#pragma unroll
        for (int i = 0; i < 4; i++) {
            const int gi = i * 256 + t;
            const int k = gi >> 5, nq = gi & 31;
            cp16(bbase + (unsigned)(k * 136 + nq * 4) * 4u,
                 Bb + (size_t)k * 1024 + nq * 4);
        }
    };

    stage(0, 0);
    CP_COMMIT();

    for (int kc = 0; kc < 32; kc++) {
        stage(kc + 1 < 32 ? kc + 1 : 31, (kc + 1) & 1);
        CP_COMMIT();
        CP_WAIT(1);
        __syncthreads();
        const float* Asb = smg + ((kc & 1) ? GA1 : GA0);
        const float* Bsb = smg + ((kc & 1) ? GB1 : GB0);
#pragma unroll
        for (int ks = 0; ks < 4; ks++) {
            unsigned bh[4][2], bl[4][2];
#pragma unroll
            for (int nf = 0; nf < 4; nf++) {
                const float* bp = Bsb + (ks * 8 + tig) * 136 + n0w + nf * 8 + g;
                float b0 = bp[0], b1 = bp[4 * 136];
                bh[nf][0] = f2tf(b0);
                bh[nf][1] = f2tf(b1);
                if (SPLIT == 3) {
                    bl[nf][0] = f2tf(b0 - __uint_as_float(bh[nf][0]));
                    bl[nf][1] = f2tf(b1 - __uint_as_float(bh[nf][1]));
                }
            }
#pragma unroll
            for (int mf = 0; mf < 4; mf++) {
                const float* ap  = Asb + (m0w + mf * 16 + g) * 32;
                const float* ap8 = ap + 8 * 32;
                const int q0 = 4 * ((2 * ks) ^ g), q1 = 4 * ((2 * ks + 1) ^ g);
                float a0 = ap[q0 + tig], a1 = ap8[q0 + tig];
                float a2 = ap[q1 + tig], a3 = ap8[q1 + tig];
                unsigned h0 = f2tf(a0), h1 = f2tf(a1), h2 = f2tf(a2), h3 = f2tf(a3);
                unsigned l0 = 0, l1 = 0, l2 = 0, l3 = 0;
                if (SPLIT == 3) {
                    l0 = f2tf(a0 - __uint_as_float(h0));
                    l1 = f2tf(a1 - __uint_as_float(h1));
                    l2 = f2tf(a2 - __uint_as_float(h2));
                    l3 = f2tf(a3 - __uint_as_float(h3));
                }
#pragma unroll
                for (int nf = 0; nf < 4; nf++) {
                    mma_tf32(acc[mf][nf][0], acc[mf][nf][1], acc[mf][nf][2], acc[mf][nf][3],
                             h0, h1, h2, h3, bh[nf][0], bh[nf][1]);
                    if (SPLIT == 3) {
                        mma_tf32(acc[mf][nf][0], acc[mf][nf][1], acc[mf][nf][2], acc[mf][nf][3],
                                 h0, h1, h2, h3, bl[nf][0], bl[nf][1]);
                        mma_tf32(acc[mf][nf][0], acc[mf][nf][1], acc[mf][nf][2], acc[mf][nf][3],
                                 l0, l1, l2, l3, bh[nf][0], bh[nf][1]);
                    }
                }
            }
        }
        __syncthreads();
    }

#pragma unroll
    for (int mf = 0; mf < 4; mf++)
#pragma unroll
        for (int nf = 0; nf < 4; nf++) {
            const int r0 = m0 + m0w + mf * 16 + g;
            const int col = n0 + n0w + nf * 8 + 2 * tig;
            float2 v0 = make_float2(acc[mf][nf][0], acc[mf][nf][1]);
            float2 v1 = make_float2(acc[mf][nf][2], acc[mf][nf][3]);
            if (R) {
                float2 r0v = *(const float2*)&R[(size_t)r0 * 1024 + col];
                float2 r1v = *(const float2*)&R[(size_t)(r0 + 8) * 1024 + col];
                v0.x += r0v.x; v0.y += r0v.y;
                v1.x += r1v.x; v1.y += r1v.y;
            }
            *(float2*)&C[(size_t)r0 * 1024 + col] = v0;
            *(float2*)&C[(size_t)(r0 + 8) * 1024 + col] = v1;
        }
}

// ================= fused attention, softmax over HEADS, tf32 + cp.async =====
// (identical to the 1724us-passing version)
#define KA 0
#define KB 17408
#define VV 34816
#define SS 52224
#define SM_FLOATS (52224 + 4368)
#define SM_BYTES (SM_FLOATS * 4)

__device__ __forceinline__ void stage_async(const float* __restrict__ src,
                                            unsigned dst_u32, int t) {
#pragma unroll
    for (int i = 0; i < 8; i++) {
        const int f = i * 512 + t;
        const int r = f >> 8;
        const int c = f & 255;
        const int row = ((c >> 4) << 4) + r;
        const unsigned dst = dst_u32 + (unsigned)(row * 68 + (c & 15) * 4) * 4u;
        const float* g = src + (size_t)r * 1024 + c * 4;
        asm volatile("cp.async.cg.shared.global [%0], [%1], 16;" :: "r"(dst), "l"(g));
    }
}

__global__ __launch_bounds__(512, 1)
void attn_kernel(const float* __restrict__ Q, const float* __restrict__ K,
                 const float* __restrict__ V, float* __restrict__ Ctx) {
    extern __shared__ float sm[];
    unsigned smb;
    asm("{ .reg .u64 a; cvta.to.shared.u64 a, %1; cvt.u32.u64 %0, a; }"
        : "=r"(smb) : "l"(sm));

    const int t = threadIdx.x;
    const int b = blockIdx.y;
    const int q0g = blockIdx.x << 4;

    const float* Qb = Q + ((size_t)b * 2048 + q0g) * 1024;
    const float* Kb = K + (size_t)b * 2048 * 1024;
    const float* Vb = V + (size_t)b * 2048 * 1024;

    const int h    = t >> 5;
    const int lane = t & 31;
    const int g    = lane >> 2;
    const int tig  = lane & 3;

    stage_async(Qb, smb + VV * 4u, t);
    CP_COMMIT();
    CP_WAIT(0);
    __syncthreads();

    unsigned aq[8][4];
    {
        const float* qp = &sm[VV + (h * 16 + g) * 68];
#pragma unroll
        for (int ks = 0; ks < 8; ks++) {
            aq[ks][0] = ldu(qp + ks * 8 + tig);
            aq[ks][1] = ldu(qp + 8 * 68 + ks * 8 + tig);
            aq[ks][2] = ldu(qp + ks * 8 + tig + 4);
            aq[ks][3] = ldu(qp + 8 * 68 + ks * 8 + tig + 4);
        }
    }
    stage_async(Kb, smb + KA * 4u, t);
    CP_COMMIT();
    __syncthreads();
    stage_async(Vb, smb + VV * 4u, t);
    CP_COMMIT();

    float cacc[8][4];
#pragma unroll
    for (int n = 0; n < 8; n++)
#pragma unroll
        for (int j = 0; j < 4; j++) cacc[n][j] = 0.f;

    const int sxq = t >> 4, sxk = t & 15;

    for (int kt = 0; kt < 128; kt++) {
        const int cur = (kt & 1) ? KB : KA;
        const int nxt = (kt & 1) ? KA : KB;

        CP_WAIT(1);
        __syncthreads();

#pragma unroll
        for (int nt = 0; nt < 2; nt++) {
            float c0 = 0.f, c1 = 0.f, c2 = 0.f, c3 = 0.f;
            const float* kp = &sm[cur + (h * 16 + nt * 8 + g) * 68];
#pragma unroll
            for (int ks = 0; ks < 8; ks++) {
                unsigned b0 = ldu(kp + ks * 8 + tig);
                unsigned b1 = ldu(kp + ks * 8 + tig + 4);
                mma_tf32(c0, c1, c2, c3, aq[ks][0], aq[ks][1], aq[ks][2], aq[ks][3], b0, b1);
            }
            float* sp = &sm[SS + g * 273 + (nt * 8 + 2 * tig) * 17 + h];
            sp[0]            = c0 * 0.125f;
            sp[17]           = c1 * 0.125f;
            sp[8 * 273]      = c2 * 0.125f;
            sp[8 * 273 + 17] = c3 * 0.125f;
        }

        {
            const int kt2 = (kt + 1 < 128) ? kt + 1 : 127;
            stage_async(Kb + (size_t)kt2 * 16 * 1024, smb + (unsigned)nxt * 4u, t);
            CP_COMMIT();
        }
        __syncthreads();

        if (t < 256) {
            float* p = &sm[SS + sxq * 273 + sxk * 17];
            float m = p[0];
#pragma unroll
            for (int hh = 1; hh < 16; hh++) m = fmaxf(m, p[hh]);
            float s = 0.f;
#pragma unroll
            for (int hh = 0; hh < 16; hh++) { float e = __expf(p[hh] - m); p[hh] = e; s += e; }
            float inv = 1.f / s;
#pragma unroll
            for (int hh = 0; hh < 16; hh++) p[hh] *= inv;
        }

        CP_WAIT(1);
        __syncthreads();

#pragma unroll
        for (int ks = 0; ks < 2; ks++) {
            unsigned a0 = f2tf(sm[SS + g * 273 + (ks * 8 + tig) * 17 + h]);
            unsigned a1 = f2tf(sm[SS + (g + 8) * 273 + (ks * 8 + tig) * 17 + h]);
            unsigned a2 = f2tf(sm[SS + g * 273 + (ks * 8 + tig + 4) * 17 + h]);
            unsigned a3 = f2tf(sm[SS + (g + 8) * 273 + (ks * 8 + tig + 4) * 17 + h]);
            const float* vlo = &sm[VV + (h * 16 + ks * 8 + tig) * 68];
            const float* vhi = &sm[VV + (h * 16 + ks * 8 + tig + 4) * 68];
#pragma unroll
            for (int nt = 0; nt < 8; nt++) {
                unsigned b0 = ldu(vlo + nt * 8 + g);
                unsigned b1 = ldu(vhi + nt * 8 + g);
                mma_tf32(cacc[nt][0], cacc[nt][1], cacc[nt][2], cacc[nt][3],
                         a0, a1, a2, a3, b0, b1);
            }
        }
        __syncthreads();

        if (kt + 1 < 128) {
            stage_async(Vb + (size_t)(kt + 1) * 16 * 1024, smb + VV * 4u, t);
            CP_COMMIT();
        }
    }

#pragma unroll
    for (int nt = 0; nt < 8; nt++) {
        const size_t base = ((size_t)b * 2048 + q0g + g) * 1024 + h * 64 + nt * 8 + 2 * tig;
        *(float2*)&Ctx[base]            = make_float2(cacc[nt][0], cacc[nt][1]);
        *(float2*)&Ctx[base + 8 * 1024] = make_float2(cacc[nt][2], cacc[nt][3]);
    }
}

// ================= LayerNorm over last dim (1024) =================
__global__ __launch_bounds__(256)
void ln_kernel(const float* __restrict__ x, const float* __restrict__ gamma,
               const float* __restrict__ beta, float* __restrict__ out) {
    __shared__ float red[16];
    const int row = blockIdx.x, t = threadIdx.x;
    float4 v = ((const float4*)(x + (size_t)row * 1024))[t];
    float s = v.x + v.y + v.z + v.w;
    float q = v.x * v.x + v.y * v.y + v.z * v.z + v.w * v.w;
#pragma unroll
    for (int o = 16; o > 0; o >>= 1) {
        s += __shfl_xor_sync(0xffffffffu, s, o);
        q += __shfl_xor_sync(0xffffffffu, q, o);
    }
    if ((t & 31) == 0) { red[t >> 5] = s; red[8 + (t >> 5)] = q; }
    __syncthreads();
    if (t < 8) {
        s = red[t]; q = red[8 + t];
#pragma unroll
        for (int o = 4; o > 0; o >>= 1) {
            s += __shfl_xor_sync(0xffu, s, o);
            q += __shfl_xor_sync(0xffu, q, o);
        }
        if (t == 0) { red[0] = s; red[1] = q; }
    }
    __syncthreads();
    const float mu = red[0] * (1.f / 1024.f);
    const float var = red[1] * (1.f / 1024.f) - mu * mu;
    const float inv = rsqrtf(var + 1e-5f);
    float4 g = ((const float4*)gamma)[t];
    float4 bb = ((const float4*)beta)[t];
    float4 o;
    o.x = (v.x - mu) * inv * g.x + bb.x;
    o.y = (v.y - mu) * inv * g.y + bb.y;
    o.z = (v.z - mu) * inv * g.z + bb.z;
    o.w = (v.w - mu) * inv * g.w + bb.w;
    ((float4*)(out + (size_t)row * 1024))[t] = o;
}

// ================= launch =================
extern "C" void kernel_launch(void* const* d_in, const int* in_sizes, int n_in,
                              void* d_out, int out_size) {
    const float* inQ = (const float*)d_in[0];
    const float* inK = (const float*)d_in[1];
    const float* inV = (const float*)d_in[2];
    const float* WQ  = (const float*)d_in[3];
    const float* WK  = (const float*)d_in[4];
    const float* WV  = (const float*)d_in[5];
    const float* WO  = (const float*)d_in[6];
    const float* gam = (const float*)d_in[7];
    const float* bet = (const float*)d_in[8];
    float* out = (float*)d_out;

    float* base = nullptr;
    cudaGetSymbolAddress((void**)&base, g_scratch);
    float* Qb = base;
    float* Kb = base + BUF;
    float* Vb = base + 2 * BUF;
    float* Cx = base + 3 * BUF;
    float* Xb = base + 4 * BUF;

    cudaFuncSetAttribute(gemm_tf32<3>, cudaFuncAttributeMaxDynamicSharedMemorySize, GSM_BYTES);
    cudaFuncSetAttribute(gemm_tf32<1>, cudaFuncAttributeMaxDynamicSharedMemorySize, GSM_BYTES);

    dim3 gg(8, 32);
    gemm_tf32<3><<<gg, 256, GSM_BYTES>>>(inQ, WQ, nullptr, Qb);
    gemm_tf32<3><<<gg, 256, GSM_BYTES>>>(inK, WK, nullptr, Kb);
    gemm_tf32<1><<<gg, 256, GSM_BYTES>>>(inV, WV, nullptr, Vb);

    cudaFuncSetAttribute(attn_kernel, cudaFuncAttributeMaxDynamicSharedMemorySize, SM_BYTES);
    attn_kernel<<<dim3(128, 2), 512, SM_BYTES>>>(Qb, Kb, Vb, Cx);

    gemm_tf32<1><<<gg, 256, GSM_BYTES>>>(Cx, WO, inQ, Xb);
    ln_kernel<<<4096, 256>>>(Xb, gam, bet, out);
}

// round 7
// speedup vs baseline: 2.5084x; 1.0905x over previous
#include <cuda_runtime.h>

#define BUF 4194304u
__device__ float g_scratch[5u * BUF];

// ================= common helpers =================
__device__ __forceinline__ unsigned f2tf(float f) {
    unsigned u; asm("cvt.rna.tf32.f32 %0, %1;" : "=r"(u) : "f"(f)); return u;
}
__device__ __forceinline__ unsigned ldu(const float* p) { return __float_as_uint(*p); }
__device__ __forceinline__ void mma_tf32(float& c0, float& c1, float& c2, float& c3,
                                         unsigned a0, unsigned a1, unsigned a2, unsigned a3,
                                         unsigned b0, unsigned b1) {
    asm volatile("mma.sync.aligned.m16n8k8.row.col.f32.tf32.tf32.f32 "
                 "{%0,%1,%2,%3}, {%4,%5,%6,%7}, {%8,%9}, {%0,%1,%2,%3};"
                 : "+f"(c0), "+f"(c1), "+f"(c2), "+f"(c3)
                 : "r"(a0), "r"(a1), "r"(a2), "r"(a3), "r"(b0), "r"(b1));
}
#define CP_COMMIT()  asm volatile("cp.async.commit_group;" ::: "memory")
#define CP_WAIT(N)   asm volatile("cp.async.wait_group %0;" :: "n"(N) : "memory")
__device__ __forceinline__ void cp16(unsigned dst, const float* src) {
    asm volatile("cp.async.cg.shared.global [%0], [%1], 16;" :: "r"(dst), "l"(src));
}

// ================= tf32 tensor GEMM (M=4096,N=1024,K=1024) =================
#define GA0 0
#define GA1 4096
#define GB0 8192
#define GB1 12544
#define GSM_BYTES ((12544 + 4352) * 4)

template <int SPLIT>
__global__ __launch_bounds__(256)
void gemm_tf32(const float* __restrict__ A, const float* __restrict__ B,
               const float* __restrict__ R, float* __restrict__ C) {
    extern __shared__ float smg[];
    unsigned smb;
    asm("{ .reg .u64 a; cvta.to.shared.u64 a, %1; cvt.u32.u64 %0, a; }"
        : "=r"(smb) : "l"(smg));
    const int t = threadIdx.x;
    const int n0 = blockIdx.x * 128, m0 = blockIdx.y * 128;
    const int lane = t & 31, w = t >> 5, g = lane >> 2, tig = lane & 3;
    const int m0w = (w >> 2) * 64, n0w = (w & 3) * 32;

    float acc[4][4][4];
#pragma unroll
    for (int mf = 0; mf < 4; mf++)
#pragma unroll
        for (int nf = 0; nf < 4; nf++)
#pragma unroll
            for (int r = 0; r < 4; r++) acc[mf][nf][r] = 0.f;

    auto stage = [&](int kc, int buf) {
        const float* Ab = A + (size_t)m0 * 1024 + kc * 32;
        const unsigned abase = smb + (buf ? GA1 * 4u : 0u);
#pragma unroll
        for (int i = 0; i < 4; i++) {
            const int gi = i * 256 + t;
            const int m = gi >> 3, kq = gi & 7;
            cp16(abase + (unsigned)(m * 32 + 4 * (kq ^ (m & 7))) * 4u,
                 Ab + (size_t)m * 1024 + kq * 4);
        }
        const float* Bb = B + (size_t)kc * 32 * 1024 + n0;
        const unsigned bbase = smb + (unsigned)(buf ? GB1 : GB0) * 4u;
#pragma unroll
        for (int i = 0; i < 4; i++) {
            const int gi = i * 256 + t;
            const int k = gi >> 5, nq = gi & 31;
            cp16(bbase + (unsigned)(k * 136 + nq * 4) * 4u,
                 Bb + (size_t)k * 1024 + nq * 4);
        }
    };

    stage(0, 0);
    CP_COMMIT();

    for (int kc = 0; kc < 32; kc++) {
        stage(kc + 1 < 32 ? kc + 1 : 31, (kc + 1) & 1);
        CP_COMMIT();
        CP_WAIT(1);
        __syncthreads();
        const float* Asb = smg + ((kc & 1) ? GA1 : GA0);
        const float* Bsb = smg + ((kc & 1) ? GB1 : GB0);
#pragma unroll
        for (int ks = 0; ks < 4; ks++) {
            unsigned bh[4][2], bl[4][2];
#pragma unroll
            for (int nf = 0; nf < 4; nf++) {
                const float* bp = Bsb + (ks * 8 + tig) * 136 + n0w + nf * 8 + g;
                float b0 = bp[0], b1 = bp[4 * 136];
                bh[nf][0] = f2tf(b0);
                bh[nf][1] = f2tf(b1);
                if (SPLIT == 3) {
                    bl[nf][0] = f2tf(b0 - __uint_as_float(bh[nf][0]));
                    bl[nf][1] = f2tf(b1 - __uint_as_float(bh[nf][1]));
                }
            }
#pragma unroll
            for (int mf = 0; mf < 4; mf++) {
                const float* ap  = Asb + (m0w + mf * 16 + g) * 32;
                const float* ap8 = ap + 8 * 32;
                const int q0 = 4 * ((2 * ks) ^ g), q1 = 4 * ((2 * ks + 1) ^ g);
                float a0 = ap[q0 + tig], a1 = ap8[q0 + tig];
                float a2 = ap[q1 + tig], a3 = ap8[q1 + tig];
                unsigned h0 = f2tf(a0), h1 = f2tf(a1), h2 = f2tf(a2), h3 = f2tf(a3);
                unsigned l0 = 0, l1 = 0, l2 = 0, l3 = 0;
                if (SPLIT == 3) {
                    l0 = f2tf(a0 - __uint_as_float(h0));
                    l1 = f2tf(a1 - __uint_as_float(h1));
                    l2 = f2tf(a2 - __uint_as_float(h2));
                    l3 = f2tf(a3 - __uint_as_float(h3));
                }
#pragma unroll
                for (int nf = 0; nf < 4; nf++) {
                    mma_tf32(acc[mf][nf][0], acc[mf][nf][1], acc[mf][nf][2], acc[mf][nf][3],
                             h0, h1, h2, h3, bh[nf][0], bh[nf][1]);
                    if (SPLIT == 3) {
                        mma_tf32(acc[mf][nf][0], acc[mf][nf][1], acc[mf][nf][2], acc[mf][nf][3],
                                 h0, h1, h2, h3, bl[nf][0], bl[nf][1]);
                        mma_tf32(acc[mf][nf][0], acc[mf][nf][1], acc[mf][nf][2], acc[mf][nf][3],
                                 l0, l1, l2, l3, bh[nf][0], bh[nf][1]);
                    }
                }
            }
        }
        __syncthreads();
    }

#pragma unroll
    for (int mf = 0; mf < 4; mf++)
#pragma unroll
        for (int nf = 0; nf < 4; nf++) {
            const int r0 = m0 + m0w + mf * 16 + g;
            const int col = n0 + n0w + nf * 8 + 2 * tig;
            float2 v0 = make_float2(acc[mf][nf][0], acc[mf][nf][1]);
            float2 v1 = make_float2(acc[mf][nf][2], acc[mf][nf][3]);
            if (R) {
                float2 r0v = *(const float2*)&R[(size_t)r0 * 1024 + col];
                float2 r1v = *(const float2*)&R[(size_t)(r0 + 8) * 1024 + col];
                v0.x += r0v.x; v0.y += r0v.y;
                v1.x += r1v.x; v1.y += r1v.y;
            }
            *(float2*)&C[(size_t)r0 * 1024 + col] = v0;
            *(float2*)&C[(size_t)(r0 + 8) * 1024 + col] = v1;
        }
}

// ================= fused attention, softmax over HEADS, tf32 + cp.async =====
// k-split x4 across blockIdx.z; partial contexts combined via atomicAdd.
#define KA 0
#define KB 17408
#define VV 34816
#define SS 52224
#define SM_FLOATS (52224 + 4368)
#define SM_BYTES (SM_FLOATS * 4)

__device__ __forceinline__ void stage_async(const float* __restrict__ src,
                                            unsigned dst_u32, int t) {
#pragma unroll
    for (int i = 0; i < 8; i++) {
        const int f = i * 512 + t;
        const int r = f >> 8;
        const int c = f & 255;
        const int row = ((c >> 4) << 4) + r;
        const unsigned dst = dst_u32 + (unsigned)(row * 68 + (c & 15) * 4) * 4u;
        const float* g = src + (size_t)r * 1024 + c * 4;
        asm volatile("cp.async.cg.shared.global [%0], [%1], 16;" :: "r"(dst), "l"(g));
    }
}

__global__ __launch_bounds__(512, 1)
void attn_kernel(const float* __restrict__ Q, const float* __restrict__ K,
                 const float* __restrict__ V, float* __restrict__ Ctx) {
    extern __shared__ float sm[];
    unsigned smb;
    asm("{ .reg .u64 a; cvta.to.shared.u64 a, %1; cvt.u32.u64 %0, a; }"
        : "=r"(smb) : "l"(sm));

    const int t = threadIdx.x;
    const int b = blockIdx.y;
    const int q0g = blockIdx.x << 4;
    const int k0   = blockIdx.z * 32;       // this CTA's key-tile range
    const int kend = k0 + 32;

    const float* Qb = Q + ((size_t)b * 2048 + q0g) * 1024;
    const float* Kb = K + (size_t)b * 2048 * 1024;
    const float* Vb = V + (size_t)b * 2048 * 1024;

    const int h    = t >> 5;
    const int lane = t & 31;
    const int g    = lane >> 2;
    const int tig  = lane & 3;

    stage_async(Qb, smb + VV * 4u, t);
    CP_COMMIT();
    CP_WAIT(0);
    __syncthreads();

    unsigned aq[8][4];
    {
        const float* qp = &sm[VV + (h * 16 + g) * 68];
#pragma unroll
        for (int ks = 0; ks < 8; ks++) {
            aq[ks][0] = ldu(qp + ks * 8 + tig);
            aq[ks][1] = ldu(qp + 8 * 68 + ks * 8 + tig);
            aq[ks][2] = ldu(qp + ks * 8 + tig + 4);
            aq[ks][3] = ldu(qp + 8 * 68 + ks * 8 + tig + 4);
        }
    }
    stage_async(Kb + (size_t)k0 * 16 * 1024, smb + KA * 4u, t);
    CP_COMMIT();
    __syncthreads();
    stage_async(Vb + (size_t)k0 * 16 * 1024, smb + VV * 4u, t);
    CP_COMMIT();

    float cacc[8][4];
#pragma unroll
    for (int n = 0; n < 8; n++)
#pragma unroll
        for (int j = 0; j < 4; j++) cacc[n][j] = 0.f;

    const int sxq = t >> 4, sxk = t & 15;

    for (int kt = k0; kt < kend; kt++) {
        const int cur = (kt & 1) ? KB : KA;
        const int nxt = (kt & 1) ? KA : KB;

        CP_WAIT(1);
        __syncthreads();

        // ---- scores: two 4-deep MMA chains per ntile ----
#pragma unroll
        for (int nt = 0; nt < 2; nt++) {
            float c0a = 0.f, c1a = 0.f, c2a = 0.f, c3a = 0.f;
            float c0b = 0.f, c1b = 0.f, c2b = 0.f, c3b = 0.f;
            const float* kp = &sm[cur + (h * 16 + nt * 8 + g) * 68];
#pragma unroll
            for (int ks = 0; ks < 4; ks++) {
                unsigned b0 = ldu(kp + ks * 8 + tig);
                unsigned b1 = ldu(kp + ks * 8 + tig + 4);
                mma_tf32(c0a, c1a, c2a, c3a, aq[ks][0], aq[ks][1], aq[ks][2], aq[ks][3], b0, b1);
            }
#pragma unroll
            for (int ks = 4; ks < 8; ks++) {
                unsigned b0 = ldu(kp + ks * 8 + tig);
                unsigned b1 = ldu(kp + ks * 8 + tig + 4);
                mma_tf32(c0b, c1b, c2b, c3b, aq[ks][0], aq[ks][1], aq[ks][2], aq[ks][3], b0, b1);
            }
            float* sp = &sm[SS + g * 273 + (nt * 8 + 2 * tig) * 17 + h];
            sp[0]            = (c0a + c0b) * 0.125f;
            sp[17]           = (c1a + c1b) * 0.125f;
            sp[8 * 273]      = (c2a + c2b) * 0.125f;
            sp[8 * 273 + 17] = (c3a + c3b) * 0.125f;
        }

        {
            const int kt2 = (kt + 1 < kend) ? kt + 1 : kt;
            stage_async(Kb + (size_t)kt2 * 16 * 1024, smb + (unsigned)nxt * 4u, t);
            CP_COMMIT();
        }
        __syncthreads();

        // ---- softmax over 16 heads, no max-sub (scores bounded), 4-way sums ----
        if (t < 256) {
            float* p = &sm[SS + sxq * 273 + sxk * 17];
            float s0 = 0.f, s1 = 0.f, s2 = 0.f, s3 = 0.f;
#pragma unroll
            for (int hh = 0; hh < 16; hh += 4) {
                float e0 = __expf(p[hh + 0]);
                float e1 = __expf(p[hh + 1]);
                float e2 = __expf(p[hh + 2]);
                float e3 = __expf(p[hh + 3]);
                p[hh + 0] = e0; p[hh + 1] = e1; p[hh + 2] = e2; p[hh + 3] = e3;
                s0 += e0; s1 += e1; s2 += e2; s3 += e3;
            }
            const float inv = __frcp_rn((s0 + s1) + (s2 + s3));
#pragma unroll
            for (int hh = 0; hh < 16; hh++) p[hh] *= inv;
        }

        CP_WAIT(1);
        __syncthreads();

        // ---- context ----
#pragma unroll
        for (int ks = 0; ks < 2; ks++) {
            unsigned a0 = f2tf(sm[SS + g * 273 + (ks * 8 + tig) * 17 + h]);
            unsigned a1 = f2tf(sm[SS + (g + 8) * 273 + (ks * 8 + tig) * 17 + h]);
            unsigned a2 = f2tf(sm[SS + g * 273 + (ks * 8 + tig + 4) * 17 + h]);
            unsigned a3 = f2tf(sm[SS + (g + 8) * 273 + (ks * 8 + tig + 4) * 17 + h]);
            const float* vlo = &sm[VV + (h * 16 + ks * 8 + tig) * 68];
            const float* vhi = &sm[VV + (h * 16 + ks * 8 + tig + 4) * 68];
#pragma unroll
            for (int nt = 0; nt < 8; nt++) {
                unsigned b0 = ldu(vlo + nt * 8 + g);
                unsigned b1 = ldu(vhi + nt * 8 + g);
                mma_tf32(cacc[nt][0], cacc[nt][1], cacc[nt][2], cacc[nt][3],
                         a0, a1, a2, a3, b0, b1);
            }
        }
        __syncthreads();

        if (kt + 1 < kend) {
            stage_async(Vb + (size_t)(kt + 1) * 16 * 1024, smb + VV * 4u, t);
            CP_COMMIT();
        }
    }

    // ---- accumulate partial context (4 k-splits) ----
#pragma unroll
    for (int nt = 0; nt < 8; nt++) {
        const size_t base = ((size_t)b * 2048 + q0g + g) * 1024 + h * 64 + nt * 8 + 2 * tig;
        atomicAdd(&Ctx[base + 0], cacc[nt][0]);
        atomicAdd(&Ctx[base + 1], cacc[nt][1]);
        atomicAdd(&Ctx[base + 8 * 1024 + 0], cacc[nt][2]);
        atomicAdd(&Ctx[base + 8 * 1024 + 1], cacc[nt][3]);
    }
}

// ================= LayerNorm over last dim (1024) =================
__global__ __launch_bounds__(256)
void ln_kernel(const float* __restrict__ x, const float* __restrict__ gamma,
               const float* __restrict__ beta, float* __restrict__ out) {
    __shared__ float red[16];
    const int row = blockIdx.x, t = threadIdx.x;
    float4 v = ((const float4*)(x + (size_t)row * 1024))[t];
    float s = v.x + v.y + v.z + v.w;
    float q = v.x * v.x + v.y * v.y + v.z * v.z + v.w * v.w;
#pragma unroll
    for (int o = 16; o > 0; o >>= 1) {
        s += __shfl_xor_sync(0xffffffffu, s, o);
        q += __shfl_xor_sync(0xffffffffu, q, o);
    }
    if ((t & 31) == 0) { red[t >> 5] = s; red[8 + (t >> 5)] = q; }
    __syncthreads();
    if (t < 8) {
        s = red[t]; q = red[8 + t];
#pragma unroll
        for (int o = 4; o > 0; o >>= 1) {
            s += __shfl_xor_sync(0xffu, s, o);
            q += __shfl_xor_sync(0xffu, q, o);
        }
        if (t == 0) { red[0] = s; red[1] = q; }
    }
    __syncthreads();
    const float mu = red[0] * (1.f / 1024.f);
    const float var = red[1] * (1.f / 1024.f) - mu * mu;
    const float inv = rsqrtf(var + 1e-5f);
    float4 g = ((const float4*)gamma)[t];
    float4 bb = ((const float4*)beta)[t];
    float4 o;
    o.x = (v.x - mu) * inv * g.x + bb.x;
    o.y = (v.y - mu) * inv * g.y + bb.y;
    o.z = (v.z - mu) * inv * g.z + bb.z;
    o.w = (v.w - mu) * inv * g.w + bb.w;
    ((float4*)(out + (size_t)row * 1024))[t] = o;
}

// ================= launch =================
extern "C" void kernel_launch(void* const* d_in, const int* in_sizes, int n_in,
                              void* d_out, int out_size) {
    const float* inQ = (const float*)d_in[0];
    const float* inK = (const float*)d_in[1];
    const float* inV = (const float*)d_in[2];
    const float* WQ  = (const float*)d_in[3];
    const float* WK  = (const float*)d_in[4];
    const float* WV  = (const float*)d_in[5];
    const float* WO  = (const float*)d_in[6];
    const float* gam = (const float*)d_in[7];
    const float* bet = (const float*)d_in[8];
    float* out = (float*)d_out;

    float* base = nullptr;
    cudaGetSymbolAddress((void**)&base, g_scratch);
    float* Qb = base;
    float* Kb = base + BUF;
    float* Vb = base + 2 * BUF;
    float* Cx = base + 3 * BUF;
    float* Xb = base + 4 * BUF;

    cudaFuncSetAttribute(gemm_tf32<3>, cudaFuncAttributeMaxDynamicSharedMemorySize, GSM_BYTES);
    cudaFuncSetAttribute(gemm_tf32<1>, cudaFuncAttributeMaxDynamicSharedMemorySize, GSM_BYTES);

    dim3 gg(8, 32);
    gemm_tf32<3><<<gg, 256, GSM_BYTES>>>(inQ, WQ, nullptr, Qb);
    gemm_tf32<3><<<gg, 256, GSM_BYTES>>>(inK, WK, nullptr, Kb);
    gemm_tf32<1><<<gg, 256, GSM_BYTES>>>(inV, WV, nullptr, Vb);

    cudaMemsetAsync(Cx, 0, BUF * sizeof(float));

    cudaFuncSetAttribute(attn_kernel, cudaFuncAttributeMaxDynamicSharedMemorySize, SM_BYTES);
    attn_kernel<<<dim3(128, 2, 4), 512, SM_BYTES>>>(Qb, Kb, Vb, Cx);

    gemm_tf32<1><<<gg, 256, GSM_BYTES>>>(Cx, WO, inQ, Xb);
    ln_kernel<<<4096, 256>>>(Xb, gam, bet, out);
}